// round 2
// baseline (speedup 1.0000x reference)
#include <cuda_runtime.h>
#include <cuda_bf16.h>
#include <cstdint>

// Problem constants
#define TN      2000
#define UN      50000
#define TF      16
#define NOUT    52          // 16 static + 36 emb
#define UN_PAD  50048       // 782 * 64
#define KTILES  782
#define KSPLIT  23
#define KT_PER_CTA 34       // 782 / 23
#define MT      128
#define MTILES  16          // 2048 / 128

// Device scratch (no allocations allowed)
__device__ __nv_bfloat16 g_ubT[128 * UN_PAD];          // rows 0..63: hi (row36 = ones), 64..127: lo
__device__ float g_partial[(size_t)KSPLIT * 2048 * 64];

__device__ __forceinline__ uint32_t sw128(uint32_t off) {
    return off ^ ((off >> 3) & 0x70u);
}
__device__ __forceinline__ uint32_t cvta_sh(const void* p) {
    return (uint32_t)__cvta_generic_to_shared(p);
}
__device__ __forceinline__ void ldsm_x4(uint32_t* r, uint32_t addr) {
    asm volatile("ldmatrix.sync.aligned.m8n8.x4.shared.b16 {%0,%1,%2,%3}, [%4];"
                 : "=r"(r[0]), "=r"(r[1]), "=r"(r[2]), "=r"(r[3]) : "r"(addr));
}
__device__ __forceinline__ void mma16816(float* c, const uint32_t* a, uint32_t b0, uint32_t b1) {
    asm volatile(
        "mma.sync.aligned.m16n8k16.row.col.f32.bf16.bf16.f32 "
        "{%0,%1,%2,%3}, {%4,%5,%6,%7}, {%8,%9}, {%0,%1,%2,%3};"
        : "+f"(c[0]), "+f"(c[1]), "+f"(c[2]), "+f"(c[3])
        : "r"(a[0]), "r"(a[1]), "r"(a[2]), "r"(a[3]), "r"(b0), "r"(b1));
}

// ---------------------------------------------------------------------------
// Kernel 1: build U_emb^T in split-bf16 (hi/lo), padded, with ones row at 36.
// U_static dtype is ambiguous (jnp.int64 demotes to int32 without x64): view
// as int32 words and detect the int64 layout by its all-zero high words.
// ---------------------------------------------------------------------------
__global__ void prep_kernel(const int* __restrict__ Uw,
                            const float* __restrict__ e0, const float* __restrict__ e1,
                            const float* __restrict__ e2, const float* __restrict__ e3,
                            const float* __restrict__ e4, const float* __restrict__ e5) {
    int k = blockIdx.x * 256 + threadIdx.x;
    if (k >= UN_PAD) return;

    // Layout probe: for int64 little-endian with values < 2^31, every odd
    // 4-byte word is zero. Genuine int32 indices (random in [0,size)) make
    // this test fail with probability ~1. First 129 words exist either way.
    bool is64 = true;
#pragma unroll
    for (int j = 1; j < 129; j += 2) is64 = is64 && (Uw[j] == 0);

    const int sizes[6] = {222, 27, 373, 283, 26, 7};
    float v[36];
#pragma unroll
    for (int i = 0; i < 36; i++) v[i] = 0.0f;
    if (k < UN) {
        const float* tabs[6] = {e0, e1, e2, e3, e4, e5};
#pragma unroll
        for (int f = 0; f < 6; f++) {
            int elem = k * 6 + f;
            int idx = is64 ? Uw[2 * elem] : Uw[elem];
            // clamp: no-op when detection is right; prevents traps otherwise
            idx = max(0, min(sizes[f] - 1, idx));
            const float* t = tabs[f] + (size_t)idx * 6;
#pragma unroll
            for (int d = 0; d < 6; d++) v[f * 6 + d] = t[d];
        }
    }
#pragma unroll
    for (int n = 0; n < 36; n++) {
        __nv_bfloat16 hi = __float2bfloat16(v[n]);
        float lo = v[n] - __bfloat162float(hi);
        g_ubT[(size_t)n * UN_PAD + k] = hi;
        g_ubT[(size_t)(64 + n) * UN_PAD + k] = __float2bfloat16(lo);
    }
    // ones column (counts) in hi, zero in lo; zero the padding rows
    g_ubT[(size_t)36 * UN_PAD + k] = __float2bfloat16(1.0f);
    g_ubT[(size_t)100 * UN_PAD + k] = __float2bfloat16(0.0f);
#pragma unroll
    for (int n = 37; n < 64; n++) {
        g_ubT[(size_t)n * UN_PAD + k] = __float2bfloat16(0.0f);
        g_ubT[(size_t)(64 + n) * UN_PAD + k] = __float2bfloat16(0.0f);
    }
}

// ---------------------------------------------------------------------------
// Kernel 2: mask[2000,50000] @ U_emb[50000,64] via mma.sync bf16 (hi+lo).
// Grid: (16 m-tiles, 23 k-splits). Each CTA owns an exclusive partial slab.
// ---------------------------------------------------------------------------
__global__ __launch_bounds__(256, 2) void gemm_kernel(const int* __restrict__ mask) {
    __shared__ __align__(16) __nv_bfloat16 shA[128 * 64];   // 16 KB, SW128 swizzled
    __shared__ __align__(16) __nv_bfloat16 shB[128 * 64];   // 16 KB (rows 0..63 hi, 64..127 lo)

    const int tid  = threadIdx.x;
    const int lane = tid & 31;
    const int wid  = tid >> 5;
    const int wm   = wid & 3;    // 4 warps over M
    const int wn   = wid >> 2;   // 2 warps over N
    const int mtile  = blockIdx.x;
    const int ks     = blockIdx.y;
    const int mbase  = mtile * MT;
    const int ktile0 = ks * KT_PER_CTA;

    const uint32_t shA_u = cvta_sh(shA);
    const uint32_t shB_u = cvta_sh(shB);

    int4 ra[8];  // next A tile: 128x64 int32 mask, 8 x int4 per thread
    int4 rb[4];  // next B tile: 128x64 bf16, 4 x int4 per thread

    auto load_tiles = [&](int kt) {
        const int kb = (ktile0 + kt) * 64;
#pragma unroll
        for (int i = 0; i < 8; i++) {
            int slot = tid + i * 256;
            int row = slot >> 4, c4 = slot & 15;
            int gt = mbase + row, gk = kb + c4 * 4;
            if (gt < TN && gk < UN)
                ra[i] = __ldg((const int4*)(mask + (size_t)gt * UN + gk));
            else
                ra[i] = make_int4(0, 0, 0, 0);
        }
#pragma unroll
        for (int i = 0; i < 4; i++) {
            int slot = tid + i * 256;
            int row = slot >> 3, c8 = slot & 7;
            rb[i] = *(const int4*)(const void*)(g_ubT + (size_t)row * UN_PAD + kb + c8 * 8);
        }
    };

    float acc[2][4][4];
#pragma unroll
    for (int a = 0; a < 2; a++)
#pragma unroll
        for (int b = 0; b < 4; b++)
#pragma unroll
            for (int c = 0; c < 4; c++) acc[a][b][c] = 0.0f;

    load_tiles(0);

    for (int kt = 0; kt < KT_PER_CTA; kt++) {
        // ---- stage into shared (int32 mask -> bf16 via integer IMAD trick) ----
#pragma unroll
        for (int i = 0; i < 8; i++) {
            int slot = tid + i * 256;
            int row = slot >> 4, c4 = slot & 15;
            uint32_t p0 = (uint32_t)ra[i].x * 0x3F80u + (uint32_t)ra[i].y * 0x3F800000u;
            uint32_t p1 = (uint32_t)ra[i].z * 0x3F80u + (uint32_t)ra[i].w * 0x3F800000u;
            *(uint2*)((char*)shA + sw128(row * 128 + c4 * 8)) = make_uint2(p0, p1);
        }
#pragma unroll
        for (int i = 0; i < 4; i++) {
            int slot = tid + i * 256;
            int row = slot >> 3, c8 = slot & 7;
            *(int4*)((char*)shB + sw128(row * 128 + c8 * 16)) = rb[i];
        }
        __syncthreads();

        if (kt + 1 < KT_PER_CTA) load_tiles(kt + 1);  // overlap LDG with MMA

        // ---- MMA over 4 k16-steps ----
#pragma unroll
        for (int kk = 0; kk < 4; kk++) {
            const int kb2 = kk * 32;  // 16 bf16 = 32 bytes
            uint32_t A[2][4];
#pragma unroll
            for (int mi = 0; mi < 2; mi++) {
                int row = wm * 32 + mi * 16 + (lane & 15);
                ldsm_x4(A[mi], shA_u + sw128(row * 128 + kb2 + ((lane >> 4) << 4)));
            }
#pragma unroll
            for (int nj = 0; nj < 2; nj++) {
                int nl = wn * 32 + nj * 16 + (lane & 7) + (((lane >> 4) & 1) << 3);
                uint32_t koff = kb2 + ((lane >> 3) & 1) * 16;
                uint32_t Bh[4], Bl[4];
                ldsm_x4(Bh, shB_u + sw128((uint32_t)nl * 128 + koff));
                ldsm_x4(Bl, shB_u + sw128((uint32_t)(nl + 64) * 128 + koff));
                mma16816(acc[0][nj * 2 + 0], A[0], Bh[0], Bh[1]);
                mma16816(acc[1][nj * 2 + 0], A[1], Bh[0], Bh[1]);
                mma16816(acc[0][nj * 2 + 1], A[0], Bh[2], Bh[3]);
                mma16816(acc[1][nj * 2 + 1], A[1], Bh[2], Bh[3]);
                mma16816(acc[0][nj * 2 + 0], A[0], Bl[0], Bl[1]);
                mma16816(acc[1][nj * 2 + 0], A[1], Bl[0], Bl[1]);
                mma16816(acc[0][nj * 2 + 1], A[0], Bl[2], Bl[3]);
                mma16816(acc[1][nj * 2 + 1], A[1], Bl[2], Bl[3]);
            }
        }
        __syncthreads();
    }

    // ---- epilogue: exclusive partial slab, plain stores ----
#pragma unroll
    for (int mi = 0; mi < 2; mi++)
#pragma unroll
        for (int nc = 0; nc < 4; nc++) {
            int lm = wm * 32 + mi * 16 + (lane >> 2);
            int gm = mbase + lm;
            int gn = wn * 32 + nc * 8 + (lane & 3) * 2;
            float* d0 = &g_partial[((size_t)ks * 2048 + gm) * 64 + gn];
            *(float2*)d0 = make_float2(acc[mi][nc][0], acc[mi][nc][1]);
            float* d1 = &g_partial[((size_t)ks * 2048 + gm + 8) * 64 + gn];
            *(float2*)d1 = make_float2(acc[mi][nc][2], acc[mi][nc][3]);
        }
}

// ---------------------------------------------------------------------------
// Kernel 3: reduce k-splits, divide by counts (ones column), prepend statics.
// ---------------------------------------------------------------------------
__global__ void finalize_kernel(const float* __restrict__ Ts, float* __restrict__ out) {
    int t = blockIdx.x;
    int n = threadIdx.x;  // 64 threads
    __shared__ float sv[40];
    if (n < 37) {
        float s = 0.0f;
#pragma unroll
        for (int ksp = 0; ksp < KSPLIT; ksp++)
            s += g_partial[((size_t)ksp * 2048 + t) * 64 + n];
        sv[n] = s;
    }
    __syncthreads();
    if (n < 36) {
        out[(size_t)t * NOUT + TF + n] = sv[n] / sv[36];
    } else if (n < 36 + TF) {
        int i = n - 36;
        out[(size_t)t * NOUT + i] = Ts[(size_t)t * TF + i];
    }
}

// ---------------------------------------------------------------------------
// Inputs (metadata order): T_static f32[2000,16], U_static int (see prep),
// team_user_matrix i32[2000,50000], emb0..emb5 f32. Output f32[2000,52].
// ---------------------------------------------------------------------------
extern "C" void kernel_launch(void* const* d_in, const int* in_sizes, int n_in,
                              void* d_out, int out_size) {
    const float* Ts   = (const float*)d_in[0];
    const int*   Uw   = (const int*)d_in[1];
    const int*   mask = (const int*)d_in[2];
    const float* e0 = (const float*)d_in[3];
    const float* e1 = (const float*)d_in[4];
    const float* e2 = (const float*)d_in[5];
    const float* e3 = (const float*)d_in[6];
    const float* e4 = (const float*)d_in[7];
    const float* e5 = (const float*)d_in[8];
    float* out = (float*)d_out;

    prep_kernel<<<(UN_PAD + 255) / 256, 256>>>(Uw, e0, e1, e2, e3, e4, e5);
    dim3 grid(MTILES, KSPLIT);
    gemm_kernel<<<grid, 256>>>(mask);
    finalize_kernel<<<TN, 64>>>(Ts, out);
}

// round 3
// speedup vs baseline: 1.3600x; 1.3600x over previous
#include <cuda_runtime.h>
#include <cuda_bf16.h>
#include <cstdint>

// Problem constants
#define TN      2000
#define UN      50000
#define TF      16
#define NOUT    52          // 16 static + 36 emb
#define UN_PAD  50048       // 782 * 64
#define KTILES  782
#define KSPLIT  18          // 16 mtiles * 18 = 288 CTAs = one full wave at occ 2
#define MT      128
#define MTILES  16          // 2048 / 128

// Device scratch (no allocations allowed)
__device__ __nv_bfloat16 g_ubT[128 * UN_PAD];          // rows 0..63: hi (row36 = ones), 64..127: lo
__device__ float g_partial[(size_t)KSPLIT * 2048 * 64];

__device__ __forceinline__ uint32_t sw128(uint32_t off) {
    return off ^ ((off >> 3) & 0x70u);
}
__device__ __forceinline__ uint32_t cvta_sh(const void* p) {
    return (uint32_t)__cvta_generic_to_shared(p);
}
__device__ __forceinline__ void ldsm_x4(uint32_t* r, uint32_t addr) {
    asm volatile("ldmatrix.sync.aligned.m8n8.x4.shared.b16 {%0,%1,%2,%3}, [%4];"
                 : "=r"(r[0]), "=r"(r[1]), "=r"(r[2]), "=r"(r[3]) : "r"(addr));
}
__device__ __forceinline__ void mma16816(float* c, const uint32_t* a, uint32_t b0, uint32_t b1) {
    asm volatile(
        "mma.sync.aligned.m16n8k16.row.col.f32.bf16.bf16.f32 "
        "{%0,%1,%2,%3}, {%4,%5,%6,%7}, {%8,%9}, {%0,%1,%2,%3};"
        : "+f"(c[0]), "+f"(c[1]), "+f"(c[2]), "+f"(c[3])
        : "r"(a[0]), "r"(a[1]), "r"(a[2]), "r"(a[3]), "r"(b0), "r"(b1));
}

// ---------------------------------------------------------------------------
// Kernel 1: build U_emb^T in split-bf16 (hi/lo), padded, with ones row at 36.
// U_static dtype is ambiguous (jnp.int64 demotes to int32 without x64): view
// as int32 words and detect the int64 layout by its all-zero high words.
// ---------------------------------------------------------------------------
__global__ void prep_kernel(const int* __restrict__ Uw,
                            const float* __restrict__ e0, const float* __restrict__ e1,
                            const float* __restrict__ e2, const float* __restrict__ e3,
                            const float* __restrict__ e4, const float* __restrict__ e5) {
    int k = blockIdx.x * 256 + threadIdx.x;
    if (k >= UN_PAD) return;

    bool is64 = true;
#pragma unroll
    for (int j = 1; j < 129; j += 2) is64 = is64 && (Uw[j] == 0);

    const int sizes[6] = {222, 27, 373, 283, 26, 7};
    float v[36];
#pragma unroll
    for (int i = 0; i < 36; i++) v[i] = 0.0f;
    if (k < UN) {
        const float* tabs[6] = {e0, e1, e2, e3, e4, e5};
#pragma unroll
        for (int f = 0; f < 6; f++) {
            int elem = k * 6 + f;
            int idx = is64 ? Uw[2 * elem] : Uw[elem];
            idx = max(0, min(sizes[f] - 1, idx));
            const float* t = tabs[f] + (size_t)idx * 6;
#pragma unroll
            for (int d = 0; d < 6; d++) v[f * 6 + d] = t[d];
        }
    }
#pragma unroll
    for (int n = 0; n < 36; n++) {
        __nv_bfloat16 hi = __float2bfloat16(v[n]);
        float lo = v[n] - __bfloat162float(hi);
        g_ubT[(size_t)n * UN_PAD + k] = hi;
        g_ubT[(size_t)(64 + n) * UN_PAD + k] = __float2bfloat16(lo);
    }
    g_ubT[(size_t)36 * UN_PAD + k] = __float2bfloat16(1.0f);
    g_ubT[(size_t)100 * UN_PAD + k] = __float2bfloat16(0.0f);
#pragma unroll
    for (int n = 37; n < 64; n++) {
        g_ubT[(size_t)n * UN_PAD + k] = __float2bfloat16(0.0f);
        g_ubT[(size_t)(64 + n) * UN_PAD + k] = __float2bfloat16(0.0f);
    }
}

// ---------------------------------------------------------------------------
// Kernel 2: mask[2000,50000] @ U_emb[50000,64] via mma.sync bf16 (hi+lo).
// Grid: (16 m-tiles, 18 k-splits) = 288 CTAs = exactly one wave at occ 2.
// Double-buffered smem, ONE __syncthreads per k-tile.
// ---------------------------------------------------------------------------
extern __shared__ __align__(16) char dynsmem[];

__global__ __launch_bounds__(256, 2) void gemm_kernel(const int* __restrict__ mask) {
    // layout: A0 [0,16K) A1 [16K,32K) B0 [32K,48K) B1 [48K,64K)
    const int tid  = threadIdx.x;
    const int lane = tid & 31;
    const int wid  = tid >> 5;
    const int wm   = wid & 3;    // 4 warps over M
    const int wn   = wid >> 2;   // 2 warps over N
    const int mtile  = blockIdx.x;
    const int ks     = blockIdx.y;
    const int mbase  = mtile * MT;
    const int ktile0 = ks * 43 + min(ks, 8);
    const int cnt    = 43 + (ks < 8 ? 1 : 0);

    const uint32_t smem_u = cvta_sh(dynsmem);
    const uint32_t shA_u[2] = {smem_u, smem_u + 16384};
    const uint32_t shB_u[2] = {smem_u + 32768, smem_u + 49152};

    int4 ra[8];  // next A tile: 128x64 int32 mask, 8 x int4 per thread
    int4 rb[4];  // next B tile: 128x64 bf16, 4 x int4 per thread

    auto load_regs = [&](int kt) {
        const int kb = (ktile0 + kt) * 64;
#pragma unroll
        for (int i = 0; i < 8; i++) {
            int slot = tid + i * 256;
            int row = slot >> 4, c4 = slot & 15;
            int gt = mbase + row, gk = kb + c4 * 4;
            if (gt < TN && gk < UN)
                ra[i] = __ldg((const int4*)(mask + (size_t)gt * UN + gk));
            else
                ra[i] = make_int4(0, 0, 0, 0);
        }
#pragma unroll
        for (int i = 0; i < 4; i++) {
            int slot = tid + i * 256;
            int row = slot >> 3, c8 = slot & 7;
            rb[i] = *(const int4*)(const void*)(g_ubT + (size_t)row * UN_PAD + kb + c8 * 8);
        }
    };

    auto sts_tiles = [&](int buf) {
#pragma unroll
        for (int i = 0; i < 8; i++) {
            int slot = tid + i * 256;
            int row = slot >> 4, c4 = slot & 15;
            uint32_t p0 = (uint32_t)ra[i].x * 0x3F80u + (uint32_t)ra[i].y * 0x3F800000u;
            uint32_t p1 = (uint32_t)ra[i].z * 0x3F80u + (uint32_t)ra[i].w * 0x3F800000u;
            uint32_t a = shA_u[buf] + sw128(row * 128 + c4 * 8);
            asm volatile("st.shared.v2.b32 [%0], {%1,%2};" :: "r"(a), "r"(p0), "r"(p1));
        }
#pragma unroll
        for (int i = 0; i < 4; i++) {
            int slot = tid + i * 256;
            int row = slot >> 3, c8 = slot & 7;
            uint32_t a = shB_u[buf] + sw128(row * 128 + c8 * 16);
            asm volatile("st.shared.v4.b32 [%0], {%1,%2,%3,%4};"
                         :: "r"(a), "r"(rb[i].x), "r"(rb[i].y), "r"(rb[i].z), "r"(rb[i].w));
        }
    };

    float acc[2][4][4];
#pragma unroll
    for (int a = 0; a < 2; a++)
#pragma unroll
        for (int b = 0; b < 4; b++)
#pragma unroll
            for (int c = 0; c < 4; c++) acc[a][b][c] = 0.0f;

    load_regs(0);
    sts_tiles(0);
    if (cnt > 1) load_regs(1);
    __syncthreads();

    for (int kt = 0; kt < cnt; kt++) {
        const int cur = kt & 1;
        if (kt + 1 < cnt) sts_tiles(cur ^ 1);   // stage next tile into other buffer
        if (kt + 2 < cnt) load_regs(kt + 2);    // LDGs overlap the MMAs below

        // ---- MMA over 4 k16-steps on buffer `cur` ----
#pragma unroll
        for (int kk = 0; kk < 4; kk++) {
            const int kb2 = kk * 32;  // 16 bf16 = 32 bytes
            uint32_t A[2][4];
#pragma unroll
            for (int mi = 0; mi < 2; mi++) {
                int row = wm * 32 + mi * 16 + (lane & 15);
                ldsm_x4(A[mi], shA_u[cur] + sw128(row * 128 + kb2 + ((lane >> 4) << 4)));
            }
#pragma unroll
            for (int nj = 0; nj < 2; nj++) {
                int nl = wn * 32 + nj * 16 + (lane & 7) + (((lane >> 4) & 1) << 3);
                uint32_t koff = kb2 + ((lane >> 3) & 1) * 16;
                uint32_t Bh[4], Bl[4];
                ldsm_x4(Bh, shB_u[cur] + sw128((uint32_t)nl * 128 + koff));
                ldsm_x4(Bl, shB_u[cur] + sw128((uint32_t)(nl + 64) * 128 + koff));
                mma16816(acc[0][nj * 2 + 0], A[0], Bh[0], Bh[1]);
                mma16816(acc[1][nj * 2 + 0], A[1], Bh[0], Bh[1]);
                mma16816(acc[0][nj * 2 + 1], A[0], Bh[2], Bh[3]);
                mma16816(acc[1][nj * 2 + 1], A[1], Bh[2], Bh[3]);
                mma16816(acc[0][nj * 2 + 0], A[0], Bl[0], Bl[1]);
                mma16816(acc[1][nj * 2 + 0], A[1], Bl[0], Bl[1]);
                mma16816(acc[0][nj * 2 + 1], A[0], Bl[2], Bl[3]);
                mma16816(acc[1][nj * 2 + 1], A[1], Bl[2], Bl[3]);
            }
        }
        __syncthreads();   // next iter's sts may overwrite buffer cur^1's reader state
    }

    // ---- epilogue: exclusive partial slab, plain stores ----
#pragma unroll
    for (int mi = 0; mi < 2; mi++)
#pragma unroll
        for (int nc = 0; nc < 4; nc++) {
            int lm = wm * 32 + mi * 16 + (lane >> 2);
            int gm = mbase + lm;
            int gn = wn * 32 + nc * 8 + (lane & 3) * 2;
            float* d0 = &g_partial[((size_t)ks * 2048 + gm) * 64 + gn];
            *(float2*)d0 = make_float2(acc[mi][nc][0], acc[mi][nc][1]);
            float* d1 = &g_partial[((size_t)ks * 2048 + gm + 8) * 64 + gn];
            *(float2*)d1 = make_float2(acc[mi][nc][2], acc[mi][nc][3]);
        }
}

// ---------------------------------------------------------------------------
// Kernel 3: reduce k-splits, divide by counts (ones column), prepend statics.
// ---------------------------------------------------------------------------
__global__ void finalize_kernel(const float* __restrict__ Ts, float* __restrict__ out) {
    int t = blockIdx.x;
    int n = threadIdx.x;  // 64 threads
    __shared__ float sv[40];
    if (n < 37) {
        float s = 0.0f;
#pragma unroll
        for (int ksp = 0; ksp < KSPLIT; ksp++)
            s += g_partial[((size_t)ksp * 2048 + t) * 64 + n];
        sv[n] = s;
    }
    __syncthreads();
    if (n < 36) {
        out[(size_t)t * NOUT + TF + n] = sv[n] / sv[36];
    } else if (n < 36 + TF) {
        int i = n - 36;
        out[(size_t)t * NOUT + i] = Ts[(size_t)t * TF + i];
    }
}

// ---------------------------------------------------------------------------
// Inputs (metadata order): T_static f32[2000,16], U_static int (see prep),
// team_user_matrix i32[2000,50000], emb0..emb5 f32. Output f32[2000,52].
// ---------------------------------------------------------------------------
extern "C" void kernel_launch(void* const* d_in, const int* in_sizes, int n_in,
                              void* d_out, int out_size) {
    const float* Ts   = (const float*)d_in[0];
    const int*   Uw   = (const int*)d_in[1];
    const int*   mask = (const int*)d_in[2];
    const float* e0 = (const float*)d_in[3];
    const float* e1 = (const float*)d_in[4];
    const float* e2 = (const float*)d_in[5];
    const float* e3 = (const float*)d_in[6];
    const float* e4 = (const float*)d_in[7];
    const float* e5 = (const float*)d_in[8];
    float* out = (float*)d_out;

    static bool attr_set = false;
    if (!attr_set) {
        cudaFuncSetAttribute(gemm_kernel, cudaFuncAttributeMaxDynamicSharedMemorySize, 65536);
        attr_set = true;
    }

    prep_kernel<<<(UN_PAD + 255) / 256, 256>>>(Uw, e0, e1, e2, e3, e4, e5);
    dim3 grid(MTILES, KSPLIT);
    gemm_kernel<<<grid, 256, 65536>>>(mask);
    finalize_kernel<<<TN, 64>>>(Ts, out);
}

// round 4
// speedup vs baseline: 2.0125x; 1.4798x over previous
#include <cuda_runtime.h>
#include <cuda_fp16.h>
#include <cstdint>

// Problem constants
#define TN      2000
#define UN      50000
#define TF      16
#define NOUT    52          // 16 static + 36 emb
#define UN_PAD  50048       // 782 * 64
#define KTILES  782
#define KSPLIT  18          // 16 mtiles * 18 = 288 CTAs = one full wave at occ 2
#define MT      128
#define MTILES  16          // 2048 / 128

// Device scratch (no allocations allowed)
__device__ __half g_ubT[64 * UN_PAD];   // U_emb^T fp16: rows 0..35 emb, 36 ones, 37..63 zero
__device__ float g_partial[(size_t)KSPLIT * 2048 * 64];

__device__ __forceinline__ uint32_t sw128(uint32_t off) {
    return off ^ ((off >> 3) & 0x70u);
}
__device__ __forceinline__ uint32_t cvta_sh(const void* p) {
    return (uint32_t)__cvta_generic_to_shared(p);
}
__device__ __forceinline__ void ldsm_x4(uint32_t* r, uint32_t addr) {
    asm volatile("ldmatrix.sync.aligned.m8n8.x4.shared.b16 {%0,%1,%2,%3}, [%4];"
                 : "=r"(r[0]), "=r"(r[1]), "=r"(r[2]), "=r"(r[3]) : "r"(addr));
}
__device__ __forceinline__ void mma16816(float* c, const uint32_t* a, uint32_t b0, uint32_t b1) {
    asm volatile(
        "mma.sync.aligned.m16n8k16.row.col.f32.f16.f16.f32 "
        "{%0,%1,%2,%3}, {%4,%5,%6,%7}, {%8,%9}, {%0,%1,%2,%3};"
        : "+f"(c[0]), "+f"(c[1]), "+f"(c[2]), "+f"(c[3])
        : "r"(a[0]), "r"(a[1]), "r"(a[2]), "r"(a[3]), "r"(b0), "r"(b1));
}

// ---------------------------------------------------------------------------
// Kernel 1: build U_emb^T in fp16, padded, with ones row at 36.
// U_static dtype is ambiguous (jnp.int64 demotes to int32 without x64): view
// as int32 words and detect the int64 layout by its all-zero high words.
// ---------------------------------------------------------------------------
__global__ void prep_kernel(const int* __restrict__ Uw,
                            const float* __restrict__ e0, const float* __restrict__ e1,
                            const float* __restrict__ e2, const float* __restrict__ e3,
                            const float* __restrict__ e4, const float* __restrict__ e5) {
    int k = blockIdx.x * 256 + threadIdx.x;
    if (k >= UN_PAD) return;

    bool is64 = true;
#pragma unroll
    for (int j = 1; j < 129; j += 2) is64 = is64 && (Uw[j] == 0);

    const int sizes[6] = {222, 27, 373, 283, 26, 7};
    float v[36];
#pragma unroll
    for (int i = 0; i < 36; i++) v[i] = 0.0f;
    if (k < UN) {
        const float* tabs[6] = {e0, e1, e2, e3, e4, e5};
#pragma unroll
        for (int f = 0; f < 6; f++) {
            int elem = k * 6 + f;
            int idx = is64 ? Uw[2 * elem] : Uw[elem];
            idx = max(0, min(sizes[f] - 1, idx));
            const float* t = tabs[f] + (size_t)idx * 6;
#pragma unroll
            for (int d = 0; d < 6; d++) v[f * 6 + d] = t[d];
        }
    }
#pragma unroll
    for (int n = 0; n < 36; n++)
        g_ubT[(size_t)n * UN_PAD + k] = __float2half(v[n]);
    g_ubT[(size_t)36 * UN_PAD + k] = __float2half(1.0f);   // counts column
#pragma unroll
    for (int n = 37; n < 64; n++)
        g_ubT[(size_t)n * UN_PAD + k] = __float2half(0.0f);
}

// ---------------------------------------------------------------------------
// Kernel 2: mask[2000,50000] @ U_emb[50000,64] via mma.sync fp16 single-pass.
// Grid: (16 m-tiles, 18 k-splits) = 288 CTAs = exactly one wave at occ 2.
// Double-buffered smem, ONE __syncthreads per k-tile.
// ---------------------------------------------------------------------------
extern __shared__ __align__(16) char dynsmem[];

__global__ __launch_bounds__(256, 2) void gemm_kernel(const int* __restrict__ mask) {
    // layout: A0 [0,16K) A1 [16K,32K) B0 [32K,40K) B1 [40K,48K)
    const int tid  = threadIdx.x;
    const int lane = tid & 31;
    const int wid  = tid >> 5;
    const int wm   = wid & 3;    // 4 warps over M
    const int wn   = wid >> 2;   // 2 warps over N
    const int mtile  = blockIdx.x;
    const int ks     = blockIdx.y;
    const int mbase  = mtile * MT;
    const int ktile0 = ks * 43 + min(ks, 8);
    const int cnt    = 43 + (ks < 8 ? 1 : 0);

    const uint32_t smem_u = cvta_sh(dynsmem);
    const uint32_t shA_u[2] = {smem_u, smem_u + 16384};
    const uint32_t shB_u[2] = {smem_u + 32768, smem_u + 40960};

    int4 ra[8];  // next A tile: 128x64 int32 mask, 8 x int4 per thread
    int4 rb[2];  // next B tile: 64x64 fp16 (8 KB), 2 x int4 per thread

    auto load_regs = [&](int kt) {
        const int kb = (ktile0 + kt) * 64;
#pragma unroll
        for (int i = 0; i < 8; i++) {
            int slot = tid + i * 256;
            int row = slot >> 4, c4 = slot & 15;
            int gt = mbase + row, gk = kb + c4 * 4;
            if (gt < TN && gk < UN)
                ra[i] = __ldg((const int4*)(mask + (size_t)gt * UN + gk));
            else
                ra[i] = make_int4(0, 0, 0, 0);
        }
#pragma unroll
        for (int i = 0; i < 2; i++) {
            int slot = tid + i * 256;
            int row = slot >> 3, c8 = slot & 7;
            rb[i] = *(const int4*)(const void*)(g_ubT + (size_t)row * UN_PAD + kb + c8 * 8);
        }
    };

    auto sts_tiles = [&](int buf) {
#pragma unroll
        for (int i = 0; i < 8; i++) {
            int slot = tid + i * 256;
            int row = slot >> 4, c4 = slot & 15;
            // int32 0/1 pair -> packed fp16x2 via integer IMAD (1.0f16 = 0x3C00)
            uint32_t p0 = (uint32_t)ra[i].x * 0x3C00u + (uint32_t)ra[i].y * 0x3C000000u;
            uint32_t p1 = (uint32_t)ra[i].z * 0x3C00u + (uint32_t)ra[i].w * 0x3C000000u;
            uint32_t a = shA_u[buf] + sw128(row * 128 + c4 * 8);
            asm volatile("st.shared.v2.b32 [%0], {%1,%2};" :: "r"(a), "r"(p0), "r"(p1));
        }
#pragma unroll
        for (int i = 0; i < 2; i++) {
            int slot = tid + i * 256;
            int row = slot >> 3, c8 = slot & 7;
            uint32_t a = shB_u[buf] + sw128(row * 128 + c8 * 16);
            asm volatile("st.shared.v4.b32 [%0], {%1,%2,%3,%4};"
                         :: "r"(a), "r"(rb[i].x), "r"(rb[i].y), "r"(rb[i].z), "r"(rb[i].w));
        }
    };

    float acc[2][4][4];
#pragma unroll
    for (int a = 0; a < 2; a++)
#pragma unroll
        for (int b = 0; b < 4; b++)
#pragma unroll
            for (int c = 0; c < 4; c++) acc[a][b][c] = 0.0f;

    load_regs(0);
    sts_tiles(0);
    if (cnt > 1) load_regs(1);
    __syncthreads();

    for (int kt = 0; kt < cnt; kt++) {
        const int cur = kt & 1;
        if (kt + 1 < cnt) sts_tiles(cur ^ 1);   // stage next tile into other buffer
        if (kt + 2 < cnt) load_regs(kt + 2);    // LDGs overlap the MMAs below

        // ---- MMA over 4 k16-steps on buffer `cur` ----
#pragma unroll
        for (int kk = 0; kk < 4; kk++) {
            const int kb2 = kk * 32;  // 16 fp16 = 32 bytes
            uint32_t A[2][4];
#pragma unroll
            for (int mi = 0; mi < 2; mi++) {
                int row = wm * 32 + mi * 16 + (lane & 15);
                ldsm_x4(A[mi], shA_u[cur] + sw128(row * 128 + kb2 + ((lane >> 4) << 4)));
            }
#pragma unroll
            for (int nj = 0; nj < 2; nj++) {
                int nl = wn * 32 + nj * 16 + (lane & 7) + (((lane >> 4) & 1) << 3);
                uint32_t koff = kb2 + ((lane >> 3) & 1) * 16;
                uint32_t Bh[4];
                ldsm_x4(Bh, shB_u[cur] + sw128((uint32_t)nl * 128 + koff));
                mma16816(acc[0][nj * 2 + 0], A[0], Bh[0], Bh[1]);
                mma16816(acc[1][nj * 2 + 0], A[1], Bh[0], Bh[1]);
                mma16816(acc[0][nj * 2 + 1], A[0], Bh[2], Bh[3]);
                mma16816(acc[1][nj * 2 + 1], A[1], Bh[2], Bh[3]);
            }
        }
        __syncthreads();   // next iter's sts may overwrite buffer cur^1's reader state
    }

    // ---- epilogue: exclusive partial slab, plain stores ----
#pragma unroll
    for (int mi = 0; mi < 2; mi++)
#pragma unroll
        for (int nc = 0; nc < 4; nc++) {
            int lm = wm * 32 + mi * 16 + (lane >> 2);
            int gm = mbase + lm;
            int gn = wn * 32 + nc * 8 + (lane & 3) * 2;
            float* d0 = &g_partial[((size_t)ks * 2048 + gm) * 64 + gn];
            *(float2*)d0 = make_float2(acc[mi][nc][0], acc[mi][nc][1]);
            float* d1 = &g_partial[((size_t)ks * 2048 + gm + 8) * 64 + gn];
            *(float2*)d1 = make_float2(acc[mi][nc][2], acc[mi][nc][3]);
        }
}

// ---------------------------------------------------------------------------
// Kernel 3: reduce k-splits, divide by counts (ones column), prepend statics.
// ---------------------------------------------------------------------------
__global__ void finalize_kernel(const float* __restrict__ Ts, float* __restrict__ out) {
    int t = blockIdx.x;
    int n = threadIdx.x;  // 64 threads
    __shared__ float sv[40];
    if (n < 37) {
        float s = 0.0f;
#pragma unroll
        for (int ksp = 0; ksp < KSPLIT; ksp++)
            s += g_partial[((size_t)ksp * 2048 + t) * 64 + n];
        sv[n] = s;
    }
    __syncthreads();
    if (n < 36) {
        out[(size_t)t * NOUT + TF + n] = sv[n] / sv[36];
    } else if (n < 36 + TF) {
        int i = n - 36;
        out[(size_t)t * NOUT + i] = Ts[(size_t)t * TF + i];
    }
}

// ---------------------------------------------------------------------------
// Inputs (metadata order): T_static f32[2000,16], U_static int (see prep),
// team_user_matrix i32[2000,50000], emb0..emb5 f32. Output f32[2000,52].
// ---------------------------------------------------------------------------
extern "C" void kernel_launch(void* const* d_in, const int* in_sizes, int n_in,
                              void* d_out, int out_size) {
    const float* Ts   = (const float*)d_in[0];
    const int*   Uw   = (const int*)d_in[1];
    const int*   mask = (const int*)d_in[2];
    const float* e0 = (const float*)d_in[3];
    const float* e1 = (const float*)d_in[4];
    const float* e2 = (const float*)d_in[5];
    const float* e3 = (const float*)d_in[6];
    const float* e4 = (const float*)d_in[7];
    const float* e5 = (const float*)d_in[8];
    float* out = (float*)d_out;

    static bool attr_set = false;
    if (!attr_set) {
        cudaFuncSetAttribute(gemm_kernel, cudaFuncAttributeMaxDynamicSharedMemorySize, 49152);
        attr_set = true;
    }

    prep_kernel<<<(UN_PAD + 255) / 256, 256>>>(Uw, e0, e1, e2, e3, e4, e5);
    dim3 grid(MTILES, KSPLIT);
    gemm_kernel<<<grid, 256, 49152>>>(mask);
    finalize_kernel<<<TN, 64>>>(Ts, out);
}

// round 5
// speedup vs baseline: 2.0866x; 1.0368x over previous
#include <cuda_runtime.h>
#include <cuda_fp16.h>
#include <cstdint>

// Problem constants
#define TN      2000
#define UN      50000
#define TF      16
#define NOUT    52          // 16 static + 36 emb
#define UN_PAD  50048       // 782 * 64
#define KTILES  782
#define KSPLIT  18          // 16 mtiles * 18 = 288 CTAs = one full wave at occ 2
#define MT      128
#define MTILES  16          // 2048 / 128

// Device scratch (no allocations allowed)
__device__ __half g_ubT[64 * UN_PAD];   // U_emb^T fp16: rows 0..35 emb, 36 ones, 37..63 zero
__device__ float g_partial[(size_t)KSPLIT * 2048 * 64];

__device__ __forceinline__ uint32_t sw128(uint32_t off) {
    return off ^ ((off >> 3) & 0x70u);
}
__device__ __forceinline__ uint32_t cvta_sh(const void* p) {
    return (uint32_t)__cvta_generic_to_shared(p);
}
__device__ __forceinline__ void ldsm_x4(uint32_t* r, uint32_t addr) {
    asm volatile("ldmatrix.sync.aligned.m8n8.x4.shared.b16 {%0,%1,%2,%3}, [%4];"
                 : "=r"(r[0]), "=r"(r[1]), "=r"(r[2]), "=r"(r[3]) : "r"(addr));
}
__device__ __forceinline__ void mma16816(float* c, const uint32_t* a, uint32_t b0, uint32_t b1) {
    asm volatile(
        "mma.sync.aligned.m16n8k16.row.col.f32.f16.f16.f32 "
        "{%0,%1,%2,%3}, {%4,%5,%6,%7}, {%8,%9}, {%0,%1,%2,%3};"
        : "+f"(c[0]), "+f"(c[1]), "+f"(c[2]), "+f"(c[3])
        : "r"(a[0]), "r"(a[1]), "r"(a[2]), "r"(a[3]), "r"(b0), "r"(b1));
}

// ---------------------------------------------------------------------------
// Kernel 1: build U_emb^T in fp16. Two threads per user (halves the serial
// gather/store chain), dtype probe done once per CTA.
// ---------------------------------------------------------------------------
__global__ void prep_kernel(const int* __restrict__ Uw,
                            const float* __restrict__ e0, const float* __restrict__ e1,
                            const float* __restrict__ e2, const float* __restrict__ e3,
                            const float* __restrict__ e4, const float* __restrict__ e5) {
    __shared__ int s_is64;
    if (threadIdx.x == 0) {
        // int64 little-endian with small values -> every odd word zero.
        bool b = true;
        for (int j = 1; j < 129; j += 2) b = b && (Uw[j] == 0);
        s_is64 = b ? 1 : 0;
    }
    __syncthreads();
    const bool is64 = (s_is64 != 0);

    int slot = blockIdx.x * 256 + threadIdx.x;
    int k = slot >> 1, half = slot & 1;
    if (k >= UN_PAD) return;

    const int sizes[6] = {222, 27, 373, 283, 26, 7};
    const float* tabs[6] = {e0, e1, e2, e3, e4, e5};
    const __half hzero = __float2half(0.0f);

    if (half == 0) {
        // features 0..2 -> rows 0..17; zero rows 37..49
        float v[18];
#pragma unroll
        for (int i = 0; i < 18; i++) v[i] = 0.0f;
        if (k < UN) {
#pragma unroll
            for (int f = 0; f < 3; f++) {
                int elem = k * 6 + f;
                int idx = is64 ? Uw[2 * elem] : Uw[elem];
                idx = max(0, min(sizes[f] - 1, idx));
                const float* t = tabs[f] + (size_t)idx * 6;
#pragma unroll
                for (int d = 0; d < 6; d++) v[f * 6 + d] = t[d];
            }
        }
#pragma unroll
        for (int n = 0; n < 18; n++)
            g_ubT[(size_t)n * UN_PAD + k] = __float2half(v[n]);
#pragma unroll
        for (int n = 37; n < 50; n++)
            g_ubT[(size_t)n * UN_PAD + k] = hzero;
    } else {
        // features 3..5 -> rows 18..35; ones row 36; zero rows 50..63
        float v[18];
#pragma unroll
        for (int i = 0; i < 18; i++) v[i] = 0.0f;
        if (k < UN) {
#pragma unroll
            for (int f = 3; f < 6; f++) {
                int elem = k * 6 + f;
                int idx = is64 ? Uw[2 * elem] : Uw[elem];
                idx = max(0, min(sizes[f] - 1, idx));
                const float* t = tabs[f] + (size_t)idx * 6;
#pragma unroll
                for (int d = 0; d < 6; d++) v[(f - 3) * 6 + d] = t[d];
            }
        }
#pragma unroll
        for (int n = 0; n < 18; n++)
            g_ubT[(size_t)(18 + n) * UN_PAD + k] = __float2half(v[n]);
        g_ubT[(size_t)36 * UN_PAD + k] = __float2half(1.0f);   // counts column
#pragma unroll
        for (int n = 50; n < 64; n++)
            g_ubT[(size_t)n * UN_PAD + k] = hzero;
    }
}

// ---------------------------------------------------------------------------
// Kernel 2: mask[2000,50000] @ U_emb[50000,64] via mma.sync fp16 single-pass.
// Grid: (16 m-tiles, 18 k-splits) = 288 CTAs = exactly one wave at occ 2.
// Double-buffered smem, ONE __syncthreads per k-tile. Mask loads streaming.
// ---------------------------------------------------------------------------
extern __shared__ __align__(16) char dynsmem[];

__global__ __launch_bounds__(256, 2) void gemm_kernel(const int* __restrict__ mask) {
    // layout: A0 [0,16K) A1 [16K,32K) B0 [32K,40K) B1 [40K,48K)
    const int tid  = threadIdx.x;
    const int lane = tid & 31;
    const int wid  = tid >> 5;
    const int wm   = wid & 3;    // 4 warps over M
    const int wn   = wid >> 2;   // 2 warps over N
    const int mtile  = blockIdx.x;
    const int ks     = blockIdx.y;
    const int mbase  = mtile * MT;
    const int ktile0 = ks * 43 + min(ks, 8);
    const int cnt    = 43 + (ks < 8 ? 1 : 0);

    const uint32_t smem_u = cvta_sh(dynsmem);
    const uint32_t shA_u[2] = {smem_u, smem_u + 16384};
    const uint32_t shB_u[2] = {smem_u + 32768, smem_u + 40960};

    int4 ra[8];  // next A tile: 128x64 int32 mask, 8 x int4 per thread
    int4 rb[2];  // next B tile: 64x64 fp16 (8 KB), 2 x int4 per thread

    auto load_regs = [&](int kt) {
        const int kb = (ktile0 + kt) * 64;
#pragma unroll
        for (int i = 0; i < 8; i++) {
            int slot = tid + i * 256;
            int row = slot >> 4, c4 = slot & 15;
            int gt = mbase + row, gk = kb + c4 * 4;
            if (gt < TN && gk < UN)
                ra[i] = __ldcs((const int4*)(mask + (size_t)gt * UN + gk));  // evict-first
            else
                ra[i] = make_int4(0, 0, 0, 0);
        }
#pragma unroll
        for (int i = 0; i < 2; i++) {
            int slot = tid + i * 256;
            int row = slot >> 3, c8 = slot & 7;
            rb[i] = *(const int4*)(const void*)(g_ubT + (size_t)row * UN_PAD + kb + c8 * 8);
        }
    };

    auto sts_tiles = [&](int buf) {
#pragma unroll
        for (int i = 0; i < 8; i++) {
            int slot = tid + i * 256;
            int row = slot >> 4, c4 = slot & 15;
            // int32 0/1 pair -> packed fp16x2 via integer IMAD (1.0f16 = 0x3C00)
            uint32_t p0 = (uint32_t)ra[i].x * 0x3C00u + (uint32_t)ra[i].y * 0x3C000000u;
            uint32_t p1 = (uint32_t)ra[i].z * 0x3C00u + (uint32_t)ra[i].w * 0x3C000000u;
            uint32_t a = shA_u[buf] + sw128(row * 128 + c4 * 8);
            asm volatile("st.shared.v2.b32 [%0], {%1,%2};" :: "r"(a), "r"(p0), "r"(p1));
        }
#pragma unroll
        for (int i = 0; i < 2; i++) {
            int slot = tid + i * 256;
            int row = slot >> 3, c8 = slot & 7;
            uint32_t a = shB_u[buf] + sw128(row * 128 + c8 * 16);
            asm volatile("st.shared.v4.b32 [%0], {%1,%2,%3,%4};"
                         :: "r"(a), "r"(rb[i].x), "r"(rb[i].y), "r"(rb[i].z), "r"(rb[i].w));
        }
    };

    float acc[2][4][4];
#pragma unroll
    for (int a = 0; a < 2; a++)
#pragma unroll
        for (int b = 0; b < 4; b++)
#pragma unroll
            for (int c = 0; c < 4; c++) acc[a][b][c] = 0.0f;

    load_regs(0);
    sts_tiles(0);
    if (cnt > 1) load_regs(1);
    __syncthreads();

    for (int kt = 0; kt < cnt; kt++) {
        const int cur = kt & 1;
        if (kt + 1 < cnt) sts_tiles(cur ^ 1);   // stage next tile into other buffer
        if (kt + 2 < cnt) load_regs(kt + 2);    // LDGs overlap the MMAs below

        // ---- MMA over 4 k16-steps on buffer `cur` ----
#pragma unroll
        for (int kk = 0; kk < 4; kk++) {
            const int kb2 = kk * 32;  // 16 fp16 = 32 bytes
            uint32_t A[2][4];
#pragma unroll
            for (int mi = 0; mi < 2; mi++) {
                int row = wm * 32 + mi * 16 + (lane & 15);
                ldsm_x4(A[mi], shA_u[cur] + sw128(row * 128 + kb2 + ((lane >> 4) << 4)));
            }
#pragma unroll
            for (int nj = 0; nj < 2; nj++) {
                int nl = wn * 32 + nj * 16 + (lane & 7) + (((lane >> 4) & 1) << 3);
                uint32_t koff = kb2 + ((lane >> 3) & 1) * 16;
                uint32_t Bh[4];
                ldsm_x4(Bh, shB_u[cur] + sw128((uint32_t)nl * 128 + koff));
                mma16816(acc[0][nj * 2 + 0], A[0], Bh[0], Bh[1]);
                mma16816(acc[1][nj * 2 + 0], A[1], Bh[0], Bh[1]);
                mma16816(acc[0][nj * 2 + 1], A[0], Bh[2], Bh[3]);
                mma16816(acc[1][nj * 2 + 1], A[1], Bh[2], Bh[3]);
            }
        }
        __syncthreads();   // next iter's sts may overwrite buffer cur^1's reader state
    }

    // ---- epilogue: exclusive partial slab; skip all-zero cols >= 38 ----
#pragma unroll
    for (int mi = 0; mi < 2; mi++)
#pragma unroll
        for (int nc = 0; nc < 4; nc++) {
            int gn = wn * 32 + nc * 8 + (lane & 3) * 2;
            if (gn >= 38) continue;   // finalize only reads n < 37
            int lm = wm * 32 + mi * 16 + (lane >> 2);
            int gm = mbase + lm;
            float* d0 = &g_partial[((size_t)ks * 2048 + gm) * 64 + gn];
            *(float2*)d0 = make_float2(acc[mi][nc][0], acc[mi][nc][1]);
            float* d1 = &g_partial[((size_t)ks * 2048 + gm + 8) * 64 + gn];
            *(float2*)d1 = make_float2(acc[mi][nc][2], acc[mi][nc][3]);
        }
}

// ---------------------------------------------------------------------------
// Kernel 3: reduce k-splits, divide by counts (ones column), prepend statics.
// ---------------------------------------------------------------------------
__global__ void finalize_kernel(const float* __restrict__ Ts, float* __restrict__ out) {
    int t = blockIdx.x;
    int n = threadIdx.x;  // 64 threads
    __shared__ float sv[40];
    if (n < 37) {
        float s = 0.0f;
#pragma unroll
        for (int ksp = 0; ksp < KSPLIT; ksp++)
            s += g_partial[((size_t)ksp * 2048 + t) * 64 + n];
        sv[n] = s;
    }
    __syncthreads();
    if (n < 36) {
        out[(size_t)t * NOUT + TF + n] = sv[n] / sv[36];
    } else if (n < 36 + TF) {
        int i = n - 36;
        out[(size_t)t * NOUT + i] = Ts[(size_t)t * TF + i];
    }
}

// ---------------------------------------------------------------------------
// Inputs (metadata order): T_static f32[2000,16], U_static int (see prep),
// team_user_matrix i32[2000,50000], emb0..emb5 f32. Output f32[2000,52].
// ---------------------------------------------------------------------------
extern "C" void kernel_launch(void* const* d_in, const int* in_sizes, int n_in,
                              void* d_out, int out_size) {
    const float* Ts   = (const float*)d_in[0];
    const int*   Uw   = (const int*)d_in[1];
    const int*   mask = (const int*)d_in[2];
    const float* e0 = (const float*)d_in[3];
    const float* e1 = (const float*)d_in[4];
    const float* e2 = (const float*)d_in[5];
    const float* e3 = (const float*)d_in[6];
    const float* e4 = (const float*)d_in[7];
    const float* e5 = (const float*)d_in[8];
    float* out = (float*)d_out;

    static bool attr_set = false;
    if (!attr_set) {
        cudaFuncSetAttribute(gemm_kernel, cudaFuncAttributeMaxDynamicSharedMemorySize, 49152);
        attr_set = true;
    }

    prep_kernel<<<(UN_PAD * 2 + 255) / 256, 256>>>(Uw, e0, e1, e2, e3, e4, e5);
    dim3 grid(MTILES, KSPLIT);
    gemm_kernel<<<grid, 256, 49152>>>(mask);
    finalize_kernel<<<TN, 64>>>(Ts, out);
}